// round 15
// baseline (speedup 1.0000x reference)
#include <cuda_runtime.h>
#include <cuda_fp16.h>

#define LN 1024
#define NB 16
#define NC 512
#define KN 8
#define NCP (NC/2)

// ---- swizzle for 8-byte (float2) shared elements, banks mod 16 (block FFT) ----
__device__ __forceinline__ int cswz(int t, int i){
    if (t == 0) return i ^ (((i >> 4) & 3) | (((i >> 6) & 1) << 3));
    if (t == 1) return i ^ ((((i >> 4) & 3) << 2) | ((i >> 6) & 1));
    return i;
}

// ---------------- device scratch (statically allocated; no runtime allocs) ----------------
__device__ float2  d_tw[LN];                 // forward twiddles e^{-2pi i j/1024}
__device__ float   d_s[NB * LN];             // channel-sum of x
__device__ float2  d_qf[NB * LN];            // fft(q)
__device__ float   d_w[NB * KN * LN];        // blend weights, PRE-SCALED by 1/1024
__device__ float   d_p[NB * KN * LN];        // P = ifft((1-w)*qfft).real
__device__ float   d_sum[LN];                // BN sum per l
__device__ float   d_sq[LN];                 // BN sumsq per l
__device__ float   d_scale[LN];
__device__ float   d_shift[LN];
__device__ __half2 d_o[(size_t)NB * NCP * KN * LN];   // 128 MB o scratch, (c0,c1) packed

// ---------------- complex helpers ----------------
__device__ __forceinline__ float2 cadd(float2 a, float2 b){ return make_float2(a.x+b.x, a.y+b.y); }
__device__ __forceinline__ float2 csub(float2 a, float2 b){ return make_float2(a.x-b.x, a.y-b.y); }
__device__ __forceinline__ float2 cmul(float2 a, float2 b){ return make_float2(a.x*b.x - a.y*b.y, a.x*b.y + a.y*b.x); }

template<bool INV>
__device__ __forceinline__ float2 twg(int e){
    float2 t = d_tw[e & 1023];
    if (INV) t.y = -t.y;
    return t;
}

// =================== block-cooperative radix-4 Stockham FFT (verified) ===================
template<bool INV>
__device__ __forceinline__ void fft1024(float2 a[4], float2* s0, float2* s1, int u){
    #pragma unroll
    for (int t = 0; t < 5; t++){
        int s = 1 << (2*t);
        int q = u & (s - 1);
        int e = u - q;
        float2 b0 = cadd(a[0], a[2]);
        float2 b1 = csub(a[0], a[2]);
        float2 b2 = cadd(a[1], a[3]);
        float2 b3 = csub(a[1], a[3]);
        float2 jb3 = INV ? make_float2(-b3.y, b3.x) : make_float2(b3.y, -b3.x);
        float2 c0 = cadd(b0, b2);
        float2 c1 = cmul(cadd(b1, jb3), twg<INV>(e));
        float2 c2 = cmul(csub(b0, b2), twg<INV>(2*e));
        float2 c3 = cmul(csub(b1, jb3), twg<INV>(3*e));
        if (t < 4){
            float2* ws = (t & 1) ? s1 : s0;
            int base = 4*u - 3*q;
            ws[cswz(t, base      )] = c0;
            ws[cswz(t, base +   s)] = c1;
            ws[cswz(t, base + 2*s)] = c2;
            ws[cswz(t, base + 3*s)] = c3;
            __syncthreads();
            #pragma unroll
            for (int c = 0; c < 4; c++)
                a[c] = ws[cswz(t, u + 256*c)];
        } else {
            a[0] = c0; a[1] = c1; a[2] = c2; a[3] = c3;
        }
    }
}

// =================== warp-autonomous 32x32 FFT (verified in R4) ===================
__device__ __forceinline__ int REV5(int i){
    return ((i&1)<<4) | ((i&2)<<2) | (i&4) | ((i&8)>>2) | ((i&16)>>4);
}

__device__ __forceinline__ float2 w32f(int j){
    switch(j){
        case 0:  return make_float2( 1.f,          0.f);
        case 1:  return make_float2( 0.98078528f, -0.19509032f);
        case 2:  return make_float2( 0.92387953f, -0.38268343f);
        case 3:  return make_float2( 0.83146961f, -0.55557023f);
        case 4:  return make_float2( 0.70710678f, -0.70710678f);
        case 5:  return make_float2( 0.55557023f, -0.83146961f);
        case 6:  return make_float2( 0.38268343f, -0.92387953f);
        case 7:  return make_float2( 0.19509032f, -0.98078528f);
        case 8:  return make_float2( 0.f,         -1.f);
        case 9:  return make_float2(-0.19509032f, -0.98078528f);
        case 10: return make_float2(-0.38268343f, -0.92387953f);
        case 11: return make_float2(-0.55557023f, -0.83146961f);
        case 12: return make_float2(-0.70710678f, -0.70710678f);
        case 13: return make_float2(-0.83146961f, -0.55557023f);
        case 14: return make_float2(-0.92387953f, -0.38268343f);
        default: return make_float2(-0.98078528f, -0.19509032f);
    }
}

// In-register 32-pt DIF FFT. Natural input; output bit-reversed: r[i] = X[REV5(i)].
template<bool INV>
__device__ __forceinline__ void fft32r(float2 r[32]){
    #pragma unroll
    for (int m = 16; m >= 1; m >>= 1){
        #pragma unroll
        for (int b = 0; b < 32; b += 2*m){
            #pragma unroll
            for (int j = 0; j < m; j++){
                float2 a = r[b+j], c = r[b+j+m];
                r[b+j] = cadd(a, c);
                float2 d = csub(a, c);
                if (j == 0){
                    r[b+j+m] = d;
                } else {
                    float2 w = w32f(j * (16/m));
                    if (INV) w.y = -w.y;
                    r[b+j+m] = cmul(d, w);
                }
            }
        }
    }
}

// Warp FFT-1024. Input: r[j] = x[32*j + t]. Output: r[i] = X[t + 32*REV5(i)].
// tsh: per-warp float2[1056] scratch (33-stride transpose, conflict-free).
template<bool INV>
__device__ __forceinline__ void wfft(float2 r[32], float2* tsh, int t){
    fft32r<INV>(r);
    float2 base = d_tw[t];
    if (INV) base.y = -base.y;
    float2 w = make_float2(1.f, 0.f);
    __syncwarp();
    #pragma unroll
    for (int k1 = 0; k1 < 32; k1++){
        float2 v = cmul(r[REV5(k1)], w);
        tsh[k1*33 + t] = v;
        w = cmul(w, base);
    }
    __syncwarp();
    #pragma unroll
    for (int n2 = 0; n2 < 32; n2++)
        r[n2] = tsh[t*33 + n2];
    __syncwarp();
    fft32r<INV>(r);
}

// ---------------- kernels ----------------

__global__ void k_init(){
    int i = blockIdx.x * 256 + threadIdx.x;
    if (i < LN){
        double ang = -2.0 * 3.14159265358979323846 * (double)i / 1024.0;
        d_tw[i] = make_float2((float)cos(ang), (float)sin(ang));
        d_sum[i] = 0.f;
        d_sq[i]  = 0.f;
    }
    if (i < NB * LN) d_s[i] = 0.0f;
}

// fused: blocks [0,64) do the channel-sum of x; blocks [64,80) do fft(q)
__global__ void k_sumqf(const float* __restrict__ x, const float* __restrict__ q){
    __shared__ float2 S0[LN], S1[LN];
    int u = threadIdx.x;
    if (blockIdx.x < 64){
        int b  = blockIdx.x >> 2;
        int cg = blockIdx.x & 3;
        float acc[4] = {0.f, 0.f, 0.f, 0.f};
        const float* xb = x + ((size_t)b * NC + (size_t)cg * 128) * LN;
        for (int c = 0; c < 128; c++){
            #pragma unroll
            for (int j = 0; j < 4; j++) acc[j] += xb[(size_t)c * LN + u + 256*j];
        }
        #pragma unroll
        for (int j = 0; j < 4; j++) atomicAdd(&d_s[b * LN + u + 256*j], acc[j]);
    } else {
        int b = blockIdx.x - 64;
        float2 a[4];
        #pragma unroll
        for (int j = 0; j < 4; j++) a[j] = make_float2(q[b * LN + u + 256*j], 0.f);
        fft1024<false>(a, S0, S1, u);
        #pragma unroll
        for (int j = 0; j < 4; j++) d_qf[b * LN + u + 256*j] = a[j];
    }
}

__global__ void k_stats(const float* __restrict__ q,
                        const float* __restrict__ sig,
                        const float* __restrict__ csh){
    __shared__ float2 S0[LN], S1[LN];
    __shared__ float gsh[16];
    __shared__ float ssb[LN];
    __shared__ float red[32];
    __shared__ float scal[4];
    int k = blockIdx.x, b = blockIdx.y, u = threadIdx.x;

    float sg = sig[k] + 0.001f;
    float cc = csh[k];
    if (u < 15){
        float t = (float)u - 7.0f - cc;
        gsh[u] = expf(-0.5f * (t / sg) * (t / sg));
    }
    #pragma unroll
    for (int j = 0; j < 4; j++) ssb[u + 256*j] = d_s[b * LN + u + 256*j];
    __syncthreads();

    float gs = 0.f;
    #pragma unroll
    for (int j = 0; j < 15; j++) gs += gsh[j];
    float g[15];
    float ginv = 1.0f / (gs + 0.01f);
    #pragma unroll
    for (int j = 0; j < 15; j++) g[j] = gsh[j] * ginv;

    float2 a[4];
    #pragma unroll
    for (int c = 0; c < 4; c++){
        int l = u + 256*c;
        float bl = 0.f;
        #pragma unroll
        for (int j = 0; j < 15; j++){
            int idx = l + j - 7;
            idx = idx < 0 ? 0 : (idx > LN-1 ? LN-1 : idx);
            bl += ssb[idx] * g[j];
        }
        a[c] = make_float2(bl, 0.f);
    }

    if (u == 0){
        float mxs = 0.f, mys = 0.f;
        for (int bb2 = 0; bb2 < NB; bb2++){
            float bl0 = 0.f;
            #pragma unroll
            for (int j = 0; j < 15; j++){
                int idx = j - 7; if (idx < 0) idx = 0;
                bl0 += d_s[bb2 * LN + idx] * g[j];
            }
            mxs += bl0;
            mys += q[bb2 * LN];
        }
        scal[0] = mxs * (1.0f/16.0f);
        scal[1] = mys * (1.0f/16.0f);
    }
    __syncthreads();

    fft1024<false>(a, S0, S1, u);

    float2 qf[4];
    #pragma unroll
    for (int c = 0; c < 4; c++) qf[c] = d_qf[b * LN + u + 256*c];

    float mx = scal[0], my = scal[1];

    float v0 = 0.f, v1 = 0.f, v2 = 0.f, v3 = 0.f;
    #pragma unroll
    for (int c = 0; c < 4; c++){
        float2 vm = a[c];  vm.x -= mx;
        float2 t  = cmul(vm, vm);
        v0 += t.x; v1 += t.y;
        float2 qm = qf[c]; qm.x -= mx;
        t = cmul(qm, qm);
        v2 += t.x; v3 += t.y;
    }
    #pragma unroll
    for (int o = 16; o > 0; o >>= 1){
        v0 += __shfl_down_sync(0xffffffffu, v0, o);
        v1 += __shfl_down_sync(0xffffffffu, v1, o);
        v2 += __shfl_down_sync(0xffffffffu, v2, o);
        v3 += __shfl_down_sync(0xffffffffu, v3, o);
    }
    if ((u & 31) == 0){
        int w = u >> 5;
        red[w*4+0] = v0; red[w*4+1] = v1; red[w*4+2] = v2; red[w*4+3] = v3;
    }
    __syncthreads();
    float2 AS = make_float2(0.f, 0.f), BS = make_float2(0.f, 0.f);
    #pragma unroll
    for (int w = 0; w < 8; w++){
        AS.x += red[w*4+0]; AS.y += red[w*4+1];
        BS.x += red[w*4+2]; BS.y += red[w*4+3];
    }
    float2 dd = cmul(AS, BS);
    dd.x += 0.001f;
    float dinv = rsqrtf(dd.x*dd.x + dd.y*dd.y);

    float2 pa[4];
    #pragma unroll
    for (int c = 0; c < 4; c++){
        float2 vm = a[c];  vm.x -= mx;
        float2 qm = qf[c]; qm.x -= my;
        float2 cov = cmul(vm, qm);
        float cm = sqrtf(cov.x*cov.x + cov.y*cov.y);
        float wv = 1.0f - expf(-0.1f * cm * dinv);
        // pre-scale by 1/1024 so k_main's ifft output needs no normalization
        d_w[(b * KN + k) * LN + u + 256*c] = wv * (1.0f/1024.0f);
        float om = 1.0f - wv;
        pa[c] = make_float2(om * qf[c].x, om * qf[c].y);
    }
    __syncthreads();
    fft1024<true>(pa, S0, S1, u);
    #pragma unroll
    for (int c = 0; c < 4; c++)
        d_p[(b * KN + k) * LN + u + 256*c] = pa[c].x * (1.0f/1024.0f);
}

// -------- main kernel: block-cooperative forward + 8 warp-autonomous inverse FFTs --------
// dynamic shared layout (float2 units):
//   [0, 8448)        per-warp transpose scratch tsh (8 x 1056); first 2048 reused by fwd FFT
//   [8448, 9472)     zsh  (Z, natural order)
//   [9472, 10496)    xsh  (xa,xb packed)
//   then float[1024] osum, float[1024] osq
#define KM_SMEM_BYTES ((8*1056 + 1024 + 1024) * 8 + 2 * 1024 * 4)
__global__ void __launch_bounds__(256, 2) k_main(const float* __restrict__ x){
    extern __shared__ float2 sh[];
    float2* tsh_all = sh;
    float2* zsh = sh + 8*1056;
    float2* xsh = zsh + 1024;
    float*  osum = (float*)(xsh + 1024);
    float*  osq  = osum + 1024;

    int cp = blockIdx.x;
    int b  = blockIdx.y;
    int u  = threadIdx.x;
    int wid  = u >> 5;
    int lane = u & 31;
    const float* x0 = x + ((size_t)b * NC + 2*cp    ) * LN;
    const float* x1 = x + ((size_t)b * NC + 2*cp + 1) * LN;

    // zero BN accumulators
    #pragma unroll
    for (int j = 0; j < 4; j++){
        osum[u + 256*j] = 0.f;
        osq [u + 256*j] = 0.f;
    }

    // load x, stash to xsh, forward FFT
    float2 z[4];
    #pragma unroll
    for (int j = 0; j < 4; j++){
        float a0 = x0[u + 256*j];
        float a1 = x1[u + 256*j];
        xsh[u + 256*j] = make_float2(a0, a1);
        z[j] = make_float2(a0, a1);
    }
    fft1024<false>(z, sh, sh + 1024, u);   // uses warps 0-1's tsh region as ping-pong
    #pragma unroll
    for (int j = 0; j < 4; j++)
        zsh[u + 256*j] = z[j];
    __syncthreads();   // zsh/xsh/osum ready; fwd scratch dead

    // each warp: inverse FFT for k = wid
    int k = wid;
    float2* tsh = tsh_all + wid * 1056;
    const float* wb = d_w + ((size_t)b * KN + k) * LN;
    const float* pb = d_p + ((size_t)b * KN + k) * LN;
    __half2*     ob = d_o + (((size_t)(b * NCP + cp)) * KN + k) * LN;

    float2 r[32];
    #pragma unroll
    for (int j = 0; j < 32; j++){
        int n = 32*j + lane;
        float wv = wb[n];          // pre-scaled by 1/1024
        float2 zz = zsh[n];
        r[j] = make_float2(zz.x * wv, zz.y * wv);
    }
    wfft<true>(r, tsh, lane);      // r[i] = ifft at l = lane + 32*REV5(i)

    #pragma unroll
    for (int i = 0; i < 32; i++){
        int l = lane + 32*REV5(i);
        float pp = pb[l];
        float2 xx = xsh[l];
        float o0 = fabsf(r[i].x + pp) + xx.x;
        float o1 = fabsf(r[i].y + pp) + xx.y;
        ob[l] = __floats2half2_rn(o0, o1);
        atomicAdd(&osum[l], o0 + o1);
        atomicAdd(&osq [l], o0*o0 + o1*o1);
    }
    __syncthreads();

    // block-level BN partials -> global
    #pragma unroll
    for (int j = 0; j < 4; j++){
        int l = u + 256*j;
        atomicAdd(&d_sum[l], osum[l]);
        atomicAdd(&d_sq [l], osq [l]);
    }
}

__global__ void k_bn(const float* __restrict__ gamma, const float* __restrict__ beta){
    int l = blockIdx.x * 256 + threadIdx.x;
    if (l < LN){
        float cnt  = (float)(NB * NC * KN);   // 65536
        float mean = d_sum[l] / cnt;
        float var  = d_sq[l] / cnt - mean * mean;
        float sc = gamma[l] * rsqrtf(var + 1e-5f);
        d_scale[l] = sc;
        d_shift[l] = beta[l] - mean * sc;
    }
}

__global__ void __launch_bounds__(256) k_attn(const float* __restrict__ q, float* __restrict__ out){
    __shared__ float red[8 * 16];
    int cp = blockIdx.x, b = blockIdx.y, u = threadIdx.x;
    const __half2* ob = d_o + ((size_t)(b * NCP + cp)) * KN * LN;

    float qa[4], sc[4], sh[4];
    #pragma unroll
    for (int j = 0; j < 4; j++){
        int l = u + 256*j;
        float sl = d_scale[l];
        qa[j] = q[b * LN + l] * sl;
        sc[j] = sl;
        sh[j] = d_shift[l];
    }
    __half2 ov[KN][4];
    float s0[KN], s1[KN];
    #pragma unroll
    for (int k = 0; k < KN; k++){ s0[k] = 0.f; s1[k] = 0.f; }
    #pragma unroll
    for (int k = 0; k < KN; k++){
        #pragma unroll
        for (int j = 0; j < 4; j++){
            __half2 h = ob[k * LN + u + 256*j];
            ov[k][j] = h;
            float2 f = __half22float2(h);
            s0[k] += qa[j] * f.x;
            s1[k] += qa[j] * f.y;
        }
    }
    #pragma unroll
    for (int k = 0; k < KN; k++){
        #pragma unroll
        for (int o = 16; o > 0; o >>= 1){
            s0[k] += __shfl_down_sync(0xffffffffu, s0[k], o);
            s1[k] += __shfl_down_sync(0xffffffffu, s1[k], o);
        }
    }
    if ((u & 31) == 0){
        int w = u >> 5;
        #pragma unroll
        for (int k = 0; k < KN; k++){
            red[w * 16 + k]     = s0[k];
            red[w * 16 + 8 + k] = s1[k];
        }
    }
    __syncthreads();
    float t0[KN], t1[KN];
    #pragma unroll
    for (int k = 0; k < KN; k++){
        float a0 = 0.f, a1 = 0.f;
        #pragma unroll
        for (int w = 0; w < 8; w++){
            a0 += red[w * 16 + k];
            a1 += red[w * 16 + 8 + k];
        }
        t0[k] = a0; t1[k] = a1;
    }
    float m0 = t0[0], m1 = t1[0];
    #pragma unroll
    for (int k = 1; k < KN; k++){ m0 = fmaxf(m0, t0[k]); m1 = fmaxf(m1, t1[k]); }
    float a0[KN], a1[KN], se0 = 0.f, se1 = 0.f;
    #pragma unroll
    for (int k = 0; k < KN; k++){
        a0[k] = expf(t0[k] - m0); se0 += a0[k];
        a1[k] = expf(t1[k] - m1); se1 += a1[k];
    }
    float i0 = 1.0f / se0, i1 = 1.0f / se1;
    float* o0p = out + ((size_t)b * NC + 2*cp    ) * LN;
    float* o1p = out + ((size_t)b * NC + 2*cp + 1) * LN;
    #pragma unroll
    for (int j = 0; j < 4; j++){
        float acc0 = 0.f, acc1 = 0.f;
        #pragma unroll
        for (int k = 0; k < KN; k++){
            float2 f = __half22float2(ov[k][j]);
            acc0 += a0[k] * f.x;
            acc1 += a1[k] * f.y;
        }
        int l = u + 256*j;
        o0p[l] = sc[j] * (acc0 * i0) + sh[j];
        o1p[l] = sc[j] * (acc1 * i1) + sh[j];
    }
}

extern "C" void kernel_launch(void* const* d_in, const int* in_sizes, int n_in,
                              void* d_out, int out_size){
    const float* x     = (const float*)d_in[0];
    const float* q     = (const float*)d_in[1];
    const float* sig   = (const float*)d_in[2];
    const float* csh   = (const float*)d_in[3];
    const float* gamma = (const float*)d_in[4];
    const float* beta  = (const float*)d_in[5];
    float* out = (float*)d_out;

    cudaFuncSetAttribute(k_main, cudaFuncAttributeMaxDynamicSharedMemorySize, KM_SMEM_BYTES);

    k_init <<<64, 256>>>();
    k_sumqf<<<80, 256>>>(x, q);
    k_stats<<<dim3(KN, NB), 256>>>(q, sig, csh);
    k_main <<<dim3(NCP, NB), 256, KM_SMEM_BYTES>>>(x);
    k_bn   <<<4, 256>>>(gamma, beta);
    k_attn <<<dim3(NCP, NB), 256>>>(q, out);
}

// round 17
// speedup vs baseline: 1.2083x; 1.2083x over previous
#include <cuda_runtime.h>
#include <cuda_fp16.h>

#define LN 1024
#define NB 16
#define NC 512
#define KN 8
#define NCP (NC/2)

// ---- swizzle for 8-byte (float2) shared elements, banks mod 16 (block FFT) ----
__device__ __forceinline__ int cswz(int t, int i){
    if (t == 0) return i ^ (((i >> 4) & 3) | (((i >> 6) & 1) << 3));
    if (t == 1) return i ^ ((((i >> 4) & 3) << 2) | ((i >> 6) & 1));
    return i;
}

// ---------------- device scratch (statically allocated; no runtime allocs) ----------------
__device__ float2  d_tw[LN];                 // forward twiddles e^{-2pi i j/1024}
__device__ float   d_s[NB * LN];             // channel-sum of x
__device__ float2  d_qf[NB * LN];            // fft(q)
__device__ float   d_w[NB * KN * LN];        // blend weights, PRE-SCALED by 1/1024
__device__ float   d_p[NB * KN * LN];        // P = ifft((1-w)*qfft).real
__device__ float   d_sum[LN];                // BN sum per l
__device__ float   d_sq[LN];                 // BN sumsq per l
__device__ float   d_scale[LN];
__device__ float   d_shift[LN];
__device__ __half2 d_o[(size_t)NB * NCP * KN * LN];   // 128 MB o scratch, (c0,c1) packed

// ---------------- complex helpers ----------------
__device__ __forceinline__ float2 cadd(float2 a, float2 b){ return make_float2(a.x+b.x, a.y+b.y); }
__device__ __forceinline__ float2 csub(float2 a, float2 b){ return make_float2(a.x-b.x, a.y-b.y); }
__device__ __forceinline__ float2 cmul(float2 a, float2 b){ return make_float2(a.x*b.x - a.y*b.y, a.x*b.y + a.y*b.x); }

template<bool INV>
__device__ __forceinline__ float2 twg(int e){
    float2 t = d_tw[e & 1023];
    if (INV) t.y = -t.y;
    return t;
}

// =================== block-cooperative radix-4 Stockham FFT (verified) ===================
template<bool INV>
__device__ __forceinline__ void fft1024(float2 a[4], float2* s0, float2* s1, int u){
    #pragma unroll
    for (int t = 0; t < 5; t++){
        int s = 1 << (2*t);
        int q = u & (s - 1);
        int e = u - q;
        float2 b0 = cadd(a[0], a[2]);
        float2 b1 = csub(a[0], a[2]);
        float2 b2 = cadd(a[1], a[3]);
        float2 b3 = csub(a[1], a[3]);
        float2 jb3 = INV ? make_float2(-b3.y, b3.x) : make_float2(b3.y, -b3.x);
        float2 c0 = cadd(b0, b2);
        float2 c1 = cmul(cadd(b1, jb3), twg<INV>(e));
        float2 c2 = cmul(csub(b0, b2), twg<INV>(2*e));
        float2 c3 = cmul(csub(b1, jb3), twg<INV>(3*e));
        if (t < 4){
            float2* ws = (t & 1) ? s1 : s0;
            int base = 4*u - 3*q;
            ws[cswz(t, base      )] = c0;
            ws[cswz(t, base +   s)] = c1;
            ws[cswz(t, base + 2*s)] = c2;
            ws[cswz(t, base + 3*s)] = c3;
            __syncthreads();
            #pragma unroll
            for (int c = 0; c < 4; c++)
                a[c] = ws[cswz(t, u + 256*c)];
        } else {
            a[0] = c0; a[1] = c1; a[2] = c2; a[3] = c3;
        }
    }
}

// =================== warp-autonomous 32x32 FFT ===================
__device__ __forceinline__ int REV5(int i){
    return ((i&1)<<4) | ((i&2)<<2) | (i&4) | ((i&8)>>2) | ((i&16)>>4);
}

__device__ __forceinline__ float2 w32f(int j){
    switch(j){
        case 0:  return make_float2( 1.f,          0.f);
        case 1:  return make_float2( 0.98078528f, -0.19509032f);
        case 2:  return make_float2( 0.92387953f, -0.38268343f);
        case 3:  return make_float2( 0.83146961f, -0.55557023f);
        case 4:  return make_float2( 0.70710678f, -0.70710678f);
        case 5:  return make_float2( 0.55557023f, -0.83146961f);
        case 6:  return make_float2( 0.38268343f, -0.92387953f);
        case 7:  return make_float2( 0.19509032f, -0.98078528f);
        case 8:  return make_float2( 0.f,         -1.f);
        case 9:  return make_float2(-0.19509032f, -0.98078528f);
        case 10: return make_float2(-0.38268343f, -0.92387953f);
        case 11: return make_float2(-0.55557023f, -0.83146961f);
        case 12: return make_float2(-0.70710678f, -0.70710678f);
        case 13: return make_float2(-0.83146961f, -0.55557023f);
        case 14: return make_float2(-0.92387953f, -0.38268343f);
        default: return make_float2(-0.98078528f, -0.19509032f);
    }
}

// In-register 32-pt DIF FFT. Natural input; output bit-reversed: r[i] = X[REV5(i)].
template<bool INV>
__device__ __forceinline__ void fft32r(float2 r[32]){
    #pragma unroll
    for (int m = 16; m >= 1; m >>= 1){
        #pragma unroll
        for (int b = 0; b < 32; b += 2*m){
            #pragma unroll
            for (int j = 0; j < m; j++){
                float2 a = r[b+j], c = r[b+j+m];
                r[b+j] = cadd(a, c);
                float2 d = csub(a, c);
                if (j == 0){
                    r[b+j+m] = d;
                } else {
                    float2 w = w32f(j * (16/m));
                    if (INV) w.y = -w.y;
                    r[b+j+m] = cmul(d, w);
                }
            }
        }
    }
}

// Warp FFT-1024. Input: r[j] = x[32*j + t]. Output: r[i] = X[t + 32*REV5(i)].
// Twiddles via INDEPENDENT table lookups (t*k1 <= 961 < 1024) — no serial chain.
template<bool INV>
__device__ __forceinline__ void wfft(float2 r[32], float2* tsh, int t){
    fft32r<INV>(r);
    __syncwarp();
    #pragma unroll
    for (int k1 = 0; k1 < 32; k1++){
        float2 w = twg<INV>(t * k1);
        tsh[k1*33 + t] = cmul(r[REV5(k1)], w);
    }
    __syncwarp();
    #pragma unroll
    for (int n2 = 0; n2 < 32; n2++)
        r[n2] = tsh[t*33 + n2];
    __syncwarp();
    fft32r<INV>(r);
}

// ---------------- kernels ----------------

__global__ void k_init(){
    int i = blockIdx.x * 256 + threadIdx.x;
    if (i < LN){
        double ang = -2.0 * 3.14159265358979323846 * (double)i / 1024.0;
        d_tw[i] = make_float2((float)cos(ang), (float)sin(ang));
        d_sum[i] = 0.f;
        d_sq[i]  = 0.f;
    }
    if (i < NB * LN) d_s[i] = 0.0f;
}

// fused: blocks [0,64) do the channel-sum of x; blocks [64,80) do fft(q)
__global__ void k_sumqf(const float* __restrict__ x, const float* __restrict__ q){
    __shared__ float2 S0[LN], S1[LN];
    int u = threadIdx.x;
    if (blockIdx.x < 64){
        int b  = blockIdx.x >> 2;
        int cg = blockIdx.x & 3;
        float acc[4] = {0.f, 0.f, 0.f, 0.f};
        const float* xb = x + ((size_t)b * NC + (size_t)cg * 128) * LN;
        for (int c = 0; c < 128; c++){
            #pragma unroll
            for (int j = 0; j < 4; j++) acc[j] += xb[(size_t)c * LN + u + 256*j];
        }
        #pragma unroll
        for (int j = 0; j < 4; j++) atomicAdd(&d_s[b * LN + u + 256*j], acc[j]);
    } else {
        int b = blockIdx.x - 64;
        float2 a[4];
        #pragma unroll
        for (int j = 0; j < 4; j++) a[j] = make_float2(q[b * LN + u + 256*j], 0.f);
        fft1024<false>(a, S0, S1, u);
        #pragma unroll
        for (int j = 0; j < 4; j++) d_qf[b * LN + u + 256*j] = a[j];
    }
}

__global__ void k_stats(const float* __restrict__ q,
                        const float* __restrict__ sig,
                        const float* __restrict__ csh){
    __shared__ float2 S0[LN], S1[LN];
    __shared__ float gsh[16];
    __shared__ float ssb[LN];
    __shared__ float red[32];
    __shared__ float scal[4];
    int k = blockIdx.x, b = blockIdx.y, u = threadIdx.x;

    float sg = sig[k] + 0.001f;
    float cc = csh[k];
    if (u < 15){
        float t = (float)u - 7.0f - cc;
        gsh[u] = expf(-0.5f * (t / sg) * (t / sg));
    }
    #pragma unroll
    for (int j = 0; j < 4; j++) ssb[u + 256*j] = d_s[b * LN + u + 256*j];
    __syncthreads();

    float gs = 0.f;
    #pragma unroll
    for (int j = 0; j < 15; j++) gs += gsh[j];
    float g[15];
    float ginv = 1.0f / (gs + 0.01f);
    #pragma unroll
    for (int j = 0; j < 15; j++) g[j] = gsh[j] * ginv;

    float2 a[4];
    #pragma unroll
    for (int c = 0; c < 4; c++){
        int l = u + 256*c;
        float bl = 0.f;
        #pragma unroll
        for (int j = 0; j < 15; j++){
            int idx = l + j - 7;
            idx = idx < 0 ? 0 : (idx > LN-1 ? LN-1 : idx);
            bl += ssb[idx] * g[j];
        }
        a[c] = make_float2(bl, 0.f);
    }

    if (u == 0){
        float mxs = 0.f, mys = 0.f;
        for (int bb2 = 0; bb2 < NB; bb2++){
            float bl0 = 0.f;
            #pragma unroll
            for (int j = 0; j < 15; j++){
                int idx = j - 7; if (idx < 0) idx = 0;
                bl0 += d_s[bb2 * LN + idx] * g[j];
            }
            mxs += bl0;
            mys += q[bb2 * LN];
        }
        scal[0] = mxs * (1.0f/16.0f);
        scal[1] = mys * (1.0f/16.0f);
    }
    __syncthreads();

    fft1024<false>(a, S0, S1, u);

    float2 qf[4];
    #pragma unroll
    for (int c = 0; c < 4; c++) qf[c] = d_qf[b * LN + u + 256*c];

    float mx = scal[0], my = scal[1];

    float v0 = 0.f, v1 = 0.f, v2 = 0.f, v3 = 0.f;
    #pragma unroll
    for (int c = 0; c < 4; c++){
        float2 vm = a[c];  vm.x -= mx;
        float2 t  = cmul(vm, vm);
        v0 += t.x; v1 += t.y;
        float2 qm = qf[c]; qm.x -= mx;
        t = cmul(qm, qm);
        v2 += t.x; v3 += t.y;
    }
    #pragma unroll
    for (int o = 16; o > 0; o >>= 1){
        v0 += __shfl_down_sync(0xffffffffu, v0, o);
        v1 += __shfl_down_sync(0xffffffffu, v1, o);
        v2 += __shfl_down_sync(0xffffffffu, v2, o);
        v3 += __shfl_down_sync(0xffffffffu, v3, o);
    }
    if ((u & 31) == 0){
        int w = u >> 5;
        red[w*4+0] = v0; red[w*4+1] = v1; red[w*4+2] = v2; red[w*4+3] = v3;
    }
    __syncthreads();
    float2 AS = make_float2(0.f, 0.f), BS = make_float2(0.f, 0.f);
    #pragma unroll
    for (int w = 0; w < 8; w++){
        AS.x += red[w*4+0]; AS.y += red[w*4+1];
        BS.x += red[w*4+2]; BS.y += red[w*4+3];
    }
    float2 dd = cmul(AS, BS);
    dd.x += 0.001f;
    float dinv = rsqrtf(dd.x*dd.x + dd.y*dd.y);

    float2 pa[4];
    #pragma unroll
    for (int c = 0; c < 4; c++){
        float2 vm = a[c];  vm.x -= mx;
        float2 qm = qf[c]; qm.x -= my;
        float2 cov = cmul(vm, qm);
        float cm = sqrtf(cov.x*cov.x + cov.y*cov.y);
        float wv = 1.0f - expf(-0.1f * cm * dinv);
        // pre-scale by 1/1024 so k_main's ifft output needs no normalization
        d_w[(b * KN + k) * LN + u + 256*c] = wv * (1.0f/1024.0f);
        float om = 1.0f - wv;
        pa[c] = make_float2(om * qf[c].x, om * qf[c].y);
    }
    __syncthreads();
    fft1024<true>(pa, S0, S1, u);
    #pragma unroll
    for (int c = 0; c < 4; c++)
        d_p[(b * KN + k) * LN + u + 256*c] = pa[c].x * (1.0f/1024.0f);
}

// -------- main kernel: block-cooperative forward + 8 warp-autonomous inverse FFTs --------
// dynamic shared layout (float2 units):
//   [0, 8448)       per-warp tsh (8 x 1056): FFT transpose scratch, then reused
//                   per-warp as half2 o-row for the BN reduction
//   [8448, 9472)    zsh (Z natural order)
//   [9472, 10496)   xsh (xa,xb packed)
#define KM_SMEM_BYTES ((8*1056 + 1024 + 1024) * 8)
__global__ void __launch_bounds__(256, 2) k_main(const float* __restrict__ x){
    extern __shared__ float2 sh[];
    float2* tsh_all = sh;
    float2* zsh = sh + 8*1056;
    float2* xsh = zsh + 1024;

    int cp = blockIdx.x;
    int b  = blockIdx.y;
    int u  = threadIdx.x;
    int wid  = u >> 5;
    int lane = u & 31;
    const float* x0 = x + ((size_t)b * NC + 2*cp    ) * LN;
    const float* x1 = x + ((size_t)b * NC + 2*cp + 1) * LN;

    // load x, stash to xsh, forward FFT
    float2 z[4];
    #pragma unroll
    for (int j = 0; j < 4; j++){
        float a0 = x0[u + 256*j];
        float a1 = x1[u + 256*j];
        xsh[u + 256*j] = make_float2(a0, a1);
        z[j] = make_float2(a0, a1);
    }
    fft1024<false>(z, sh, sh + 1024, u);   // uses warps 0-1's tsh region as ping-pong
    #pragma unroll
    for (int j = 0; j < 4; j++)
        zsh[u + 256*j] = z[j];
    __syncthreads();   // zsh/xsh ready; fwd scratch dead

    // each warp: inverse FFT for k = wid
    int k = wid;
    float2* tsh = tsh_all + wid * 1056;
    const float* wb = d_w + ((size_t)b * KN + k) * LN;
    const float* pb = d_p + ((size_t)b * KN + k) * LN;
    __half2*     ob = d_o + (((size_t)(b * NCP + cp)) * KN + k) * LN;

    float2 r[32];
    #pragma unroll
    for (int j = 0; j < 32; j++){
        int n = 32*j + lane;
        float wv = wb[n];          // pre-scaled by 1/1024
        float2 zz = zsh[n];
        r[j] = make_float2(zz.x * wv, zz.y * wv);
    }
    wfft<true>(r, tsh, lane);      // r[i] = ifft at l = lane + 32*REV5(i)

    // epilogue: write o to global AND to this warp's (now dead) tsh as half2
    __half2* osh = (__half2*)tsh;
    #pragma unroll
    for (int i = 0; i < 32; i++){
        int l = lane + 32*REV5(i);
        float pp = pb[l];
        float2 xx = xsh[l];
        float o0 = fabsf(r[i].x + pp) + xx.x;
        float o1 = fabsf(r[i].y + pp) + xx.y;
        __half2 h = __floats2half2_rn(o0, o1);
        ob[l]  = h;
        osh[l] = h;
    }
    __syncthreads();

    // BN reduction: sum the 8 per-k o-rows per l (conflict-free LDS), 4 global atomics
    #pragma unroll
    for (int j = 0; j < 4; j++){
        int l = u + 256*j;
        float sm = 0.f, sq = 0.f;
        #pragma unroll
        for (int k2 = 0; k2 < KN; k2++){
            float2 f = __half22float2(((__half2*)(tsh_all + k2 * 1056))[l]);
            sm += f.x + f.y;
            sq += f.x*f.x + f.y*f.y;
        }
        atomicAdd(&d_sum[l], sm);
        atomicAdd(&d_sq [l], sq);
    }
}

__global__ void k_bn(const float* __restrict__ gamma, const float* __restrict__ beta){
    int l = blockIdx.x * 256 + threadIdx.x;
    if (l < LN){
        float cnt  = (float)(NB * NC * KN);   // 65536
        float mean = d_sum[l] / cnt;
        float var  = d_sq[l] / cnt - mean * mean;
        float sc = gamma[l] * rsqrtf(var + 1e-5f);
        d_scale[l] = sc;
        d_shift[l] = beta[l] - mean * sc;
    }
}

__global__ void __launch_bounds__(256) k_attn(const float* __restrict__ q, float* __restrict__ out){
    __shared__ float red[8 * 16];
    int cp = blockIdx.x, b = blockIdx.y, u = threadIdx.x;
    const __half2* ob = d_o + ((size_t)(b * NCP + cp)) * KN * LN;

    float qa[4], sc[4], sh[4];
    #pragma unroll
    for (int j = 0; j < 4; j++){
        int l = u + 256*j;
        float sl = d_scale[l];
        qa[j] = q[b * LN + l] * sl;
        sc[j] = sl;
        sh[j] = d_shift[l];
    }
    __half2 ov[KN][4];
    float s0[KN], s1[KN];
    #pragma unroll
    for (int k = 0; k < KN; k++){ s0[k] = 0.f; s1[k] = 0.f; }
    #pragma unroll
    for (int k = 0; k < KN; k++){
        #pragma unroll
        for (int j = 0; j < 4; j++){
            __half2 h = ob[k * LN + u + 256*j];
            ov[k][j] = h;
            float2 f = __half22float2(h);
            s0[k] += qa[j] * f.x;
            s1[k] += qa[j] * f.y;
        }
    }
    #pragma unroll
    for (int k = 0; k < KN; k++){
        #pragma unroll
        for (int o = 16; o > 0; o >>= 1){
            s0[k] += __shfl_down_sync(0xffffffffu, s0[k], o);
            s1[k] += __shfl_down_sync(0xffffffffu, s1[k], o);
        }
    }
    if ((u & 31) == 0){
        int w = u >> 5;
        #pragma unroll
        for (int k = 0; k < KN; k++){
            red[w * 16 + k]     = s0[k];
            red[w * 16 + 8 + k] = s1[k];
        }
    }
    __syncthreads();
    float t0[KN], t1[KN];
    #pragma unroll
    for (int k = 0; k < KN; k++){
        float a0 = 0.f, a1 = 0.f;
        #pragma unroll
        for (int w = 0; w < 8; w++){
            a0 += red[w * 16 + k];
            a1 += red[w * 16 + 8 + k];
        }
        t0[k] = a0; t1[k] = a1;
    }
    float m0 = t0[0], m1 = t1[0];
    #pragma unroll
    for (int k = 1; k < KN; k++){ m0 = fmaxf(m0, t0[k]); m1 = fmaxf(m1, t1[k]); }
    float a0[KN], a1[KN], se0 = 0.f, se1 = 0.f;
    #pragma unroll
    for (int k = 0; k < KN; k++){
        a0[k] = expf(t0[k] - m0); se0 += a0[k];
        a1[k] = expf(t1[k] - m1); se1 += a1[k];
    }
    float i0 = 1.0f / se0, i1 = 1.0f / se1;
    float* o0p = out + ((size_t)b * NC + 2*cp    ) * LN;
    float* o1p = out + ((size_t)b * NC + 2*cp + 1) * LN;
    #pragma unroll
    for (int j = 0; j < 4; j++){
        float acc0 = 0.f, acc1 = 0.f;
        #pragma unroll
        for (int k = 0; k < KN; k++){
            float2 f = __half22float2(ov[k][j]);
            acc0 += a0[k] * f.x;
            acc1 += a1[k] * f.y;
        }
        int l = u + 256*j;
        o0p[l] = sc[j] * (acc0 * i0) + sh[j];
        o1p[l] = sc[j] * (acc1 * i1) + sh[j];
    }
}

extern "C" void kernel_launch(void* const* d_in, const int* in_sizes, int n_in,
                              void* d_out, int out_size){
    const float* x     = (const float*)d_in[0];
    const float* q     = (const float*)d_in[1];
    const float* sig   = (const float*)d_in[2];
    const float* csh   = (const float*)d_in[3];
    const float* gamma = (const float*)d_in[4];
    const float* beta  = (const float*)d_in[5];
    float* out = (float*)d_out;

    cudaFuncSetAttribute(k_main, cudaFuncAttributeMaxDynamicSharedMemorySize, KM_SMEM_BYTES);

    k_init <<<64, 256>>>();
    k_sumqf<<<80, 256>>>(x, q);
    k_stats<<<dim3(KN, NB), 256>>>(q, sig, csh);
    k_main <<<dim3(NCP, NB), 256, KM_SMEM_BYTES>>>(x);
    k_bn   <<<4, 256>>>(gamma, beta);
    k_attn <<<dim3(NCP, NB), 256>>>(q, out);
}